// round 1
// baseline (speedup 1.0000x reference)
#include <cuda_runtime.h>

#define MAXN 100000
#define HDIM 128
#define MAXB 512
#define NHEADS 5

// ---------------- scratch (device globals; no allocation allowed) ----------
__device__ float g_agg[(size_t)MAXN * HDIM];
__device__ float g_hA [(size_t)MAXN * HDIM];
__device__ float g_hB [(size_t)MAXN * HDIM];
__device__ float g_pool[NHEADS * MAXB * HDIM];

__device__ __forceinline__ const float* sel_in(int s, const float* ext) {
    return s == 1 ? g_hA : (s == 2 ? g_hB : ext);
}

// ---------------- agg init: agg = (1+eps[layer]) * h --------------------
__global__ void init_agg_kernel(const float* __restrict__ ext, int sel,
                                const float* __restrict__ eps, int layer, int n4) {
    int i = blockIdx.x * blockDim.x + threadIdx.x;
    if (i >= n4) return;
    const float* h = sel_in(sel, ext);
    float c = 1.0f + eps[layer];
    float4 v = ((const float4*)h)[i];
    v.x *= c; v.y *= c; v.z *= c; v.w *= c;
    ((float4*)g_agg)[i] = v;
}

// ---------------- edge scatter-add: agg[dst] += h[src] ------------------
// one warp per edge; lane handles 4 floats; vector red (sm_90+)
__global__ void edge_agg_kernel(const float* __restrict__ ext, int sel,
                                const int* __restrict__ src,
                                const int* __restrict__ dst, int nE) {
    int idx = blockIdx.x * blockDim.x + threadIdx.x;
    int e = idx >> 5;
    if (e >= nE) return;
    const float* h = sel_in(sel, ext);
    int lane4 = (idx & 31) * 4;
    int s = src[e];
    int d = dst[e];
    float4 v = *(const float4*)(h + (size_t)s * HDIM + lane4);
    float* p = g_agg + (size_t)d * HDIM + lane4;
    asm volatile("red.global.add.v4.f32 [%0], {%1,%2,%3,%4};"
                 :: "l"(p), "f"(v.x), "f"(v.y), "f"(v.z), "f"(v.w)
                 : "memory");
}

// ---------------- fused GIN MLP: Y = relu(go*(relu(g1*(X@W1+b1)+bt1)@W2+b2)+bo)
// X = g_agg (already pooled+eps). 64-row tile, 256 threads, 8x4 microtile.
__global__ void __launch_bounds__(256)
mlp_kernel(float* __restrict__ extYunused, int outsel,
           const float* __restrict__ W1, const float* __restrict__ b1,
           const float* __restrict__ g1, const float* __restrict__ bt1,
           const float* __restrict__ W2, const float* __restrict__ b2,
           const float* __restrict__ go, const float* __restrict__ bo,
           int nNodes) {
    __shared__ float Xs[64 * HDIM];   // 32 KB
    __shared__ float Ws[32 * HDIM];   // 16 KB
    int t  = threadIdx.x;
    int m0 = blockIdx.x * 64;
    int rows = nNodes - m0; if (rows > 64) rows = 64;

    // load X tile (tile is a contiguous span of g_agg)
    {
        const float4* Xg = (const float4*)(g_agg + (size_t)m0 * HDIM);
        int n4 = rows * (HDIM / 4);
        #pragma unroll
        for (int i = t; i < 64 * (HDIM / 4); i += 256) {
            float4 v = (i < n4) ? Xg[i] : make_float4(0.f, 0.f, 0.f, 0.f);
            ((float4*)Xs)[i] = v;
        }
    }

    int r0 = (t >> 5) * 8;      // 8 rows per thread (warp-private band)
    int c  = (t & 31) * 4;      // 4 cols per thread
    float acc[8][4];
    #pragma unroll
    for (int r = 0; r < 8; ++r)
        #pragma unroll
        for (int i = 0; i < 4; ++i) acc[r][i] = 0.f;

    // ---- GEMM1: X @ W1 ----
    for (int kc = 0; kc < HDIM; kc += 32) {
        __syncthreads();
        const float4* Wg = (const float4*)(W1 + kc * HDIM);
        #pragma unroll
        for (int i = t; i < 32 * (HDIM / 4); i += 256) ((float4*)Ws)[i] = Wg[i];
        __syncthreads();
        #pragma unroll 8
        for (int kk = 0; kk < 32; ++kk) {
            float4 w = *(const float4*)&Ws[kk * HDIM + c];
            #pragma unroll
            for (int r = 0; r < 8; ++r) {
                float xv = Xs[(r0 + r) * HDIM + kc + kk];
                acc[r][0] += xv * w.x; acc[r][1] += xv * w.y;
                acc[r][2] += xv * w.z; acc[r][3] += xv * w.w;
            }
        }
    }
    __syncthreads();

    // epilogue1: h1 = relu(g1*(acc+b1)+bt1) -> back into Xs (warp-private rows)
    {
        float4 B  = *(const float4*)&b1[c];
        float4 G  = *(const float4*)&g1[c];
        float4 BT = *(const float4*)&bt1[c];
        #pragma unroll
        for (int r = 0; r < 8; ++r) {
            float4 v;
            v.x = fmaxf(G.x * (acc[r][0] + B.x) + BT.x, 0.f);
            v.y = fmaxf(G.y * (acc[r][1] + B.y) + BT.y, 0.f);
            v.z = fmaxf(G.z * (acc[r][2] + B.z) + BT.z, 0.f);
            v.w = fmaxf(G.w * (acc[r][3] + B.w) + BT.w, 0.f);
            *(float4*)&Xs[(r0 + r) * HDIM + c] = v;
            acc[r][0] = acc[r][1] = acc[r][2] = acc[r][3] = 0.f;
        }
    }

    // ---- GEMM2: h1 @ W2 ----
    for (int kc = 0; kc < HDIM; kc += 32) {
        __syncthreads();
        const float4* Wg = (const float4*)(W2 + kc * HDIM);
        #pragma unroll
        for (int i = t; i < 32 * (HDIM / 4); i += 256) ((float4*)Ws)[i] = Wg[i];
        __syncthreads();
        #pragma unroll 8
        for (int kk = 0; kk < 32; ++kk) {
            float4 w = *(const float4*)&Ws[kk * HDIM + c];
            #pragma unroll
            for (int r = 0; r < 8; ++r) {
                float xv = Xs[(r0 + r) * HDIM + kc + kk];
                acc[r][0] += xv * w.x; acc[r][1] += xv * w.y;
                acc[r][2] += xv * w.z; acc[r][3] += xv * w.w;
            }
        }
    }

    // epilogue2: y = relu(go*(acc+b2)+bo) -> global
    {
        float* Y = (outsel == 1) ? g_hA : g_hB;
        float4 B  = *(const float4*)&b2[c];
        float4 G  = *(const float4*)&go[c];
        float4 BO = *(const float4*)&bo[c];
        #pragma unroll
        for (int r = 0; r < 8; ++r) {
            if (r0 + r < rows) {
                float4 v;
                v.x = fmaxf(G.x * (acc[r][0] + B.x) + BO.x, 0.f);
                v.y = fmaxf(G.y * (acc[r][1] + B.y) + BO.y, 0.f);
                v.z = fmaxf(G.z * (acc[r][2] + B.z) + BO.z, 0.f);
                v.w = fmaxf(G.w * (acc[r][3] + B.w) + BO.w, 0.f);
                *(float4*)&Y[(size_t)(m0 + r0 + r) * HDIM + c] = v;
            }
        }
    }
}

// ---------------- graph pooling: contiguous segment sum -----------------
__global__ void pool_kernel(const float* __restrict__ ext, int sel,
                            int head, int npg, int nN) {
    const float* h = sel_in(sel, ext);
    int b = blockIdx.x;
    int j = threadIdx.x;  // 128 threads
    int n = b * npg;
    int end = n + npg; if (end > nN) end = nN;
    float s0 = 0.f, s1 = 0.f, s2 = 0.f, s3 = 0.f;
    for (; n + 4 <= end; n += 4) {
        s0 += h[(size_t)(n + 0) * HDIM + j];
        s1 += h[(size_t)(n + 1) * HDIM + j];
        s2 += h[(size_t)(n + 2) * HDIM + j];
        s3 += h[(size_t)(n + 3) * HDIM + j];
    }
    for (; n < end; ++n) s0 += h[(size_t)n * HDIM + j];
    g_pool[(head * gridDim.x + b) * HDIM + j] = s0 + s1 + s2 + s3;
}

// ---------------- heads: score[b,o] = sum_heads pool_h[b] @ W_h + biases --
__global__ void score_kernel(const float* __restrict__ W0,
                             const float* __restrict__ b0,
                             const float* __restrict__ W,
                             const float* __restrict__ bres,
                             float* __restrict__ out, int nB) {
    int b = blockIdx.x;
    int o = threadIdx.x >> 5;    // 10 warps
    int lane = threadIdx.x & 31;
    float s = 0.f;
    #pragma unroll
    for (int j = lane; j < HDIM; j += 32)
        s += g_pool[b * HDIM + j] * W0[j * 10 + o];
    #pragma unroll
    for (int k = 0; k < 4; ++k)
        #pragma unroll
        for (int j = lane; j < HDIM; j += 32)
            s += g_pool[((k + 1) * nB + b) * HDIM + j] * W[(k * HDIM + j) * 10 + o];
    #pragma unroll
    for (int off = 16; off; off >>= 1)
        s += __shfl_down_sync(0xffffffffu, s, off);
    if (lane == 0) {
        float bias = b0[o];
        #pragma unroll
        for (int k = 0; k < 4; ++k) bias += bres[k * 10 + o];
        out[b * 10 + o] = s + bias;
    }
}

// ---------------- launch ------------------------------------------------
extern "C" void kernel_launch(void* const* d_in, const int* in_sizes, int n_in,
                              void* d_out, int out_size) {
    const float* x        = (const float*)d_in[0];
    const int*   esrc     = (const int*)  d_in[1];
    const int*   edst     = (const int*)  d_in[2];
    const float* eps      = (const float*)d_in[4];
    const float* pre_W1   = (const float*)d_in[5];
    const float* pre_b1   = (const float*)d_in[6];
    const float* pre_g1   = (const float*)d_in[7];
    const float* pre_bt1  = (const float*)d_in[8];
    const float* pre_W2   = (const float*)d_in[9];
    const float* pre_b2   = (const float*)d_in[10];
    const float* pre_go   = (const float*)d_in[11];
    const float* pre_bo   = (const float*)d_in[12];
    const float* mlp_W1   = (const float*)d_in[13];
    const float* mlp_b1   = (const float*)d_in[14];
    const float* mlp_g1   = (const float*)d_in[15];
    const float* mlp_bt1  = (const float*)d_in[16];
    const float* mlp_W2   = (const float*)d_in[17];
    const float* mlp_b2   = (const float*)d_in[18];
    const float* bn_g     = (const float*)d_in[19];
    const float* bn_bt    = (const float*)d_in[20];
    const float* pred_W0  = (const float*)d_in[21];
    const float* pred_b0  = (const float*)d_in[22];
    const float* pred_W   = (const float*)d_in[23];
    const float* pred_b   = (const float*)d_in[24];
    float* out = (float*)d_out;

    int nN  = in_sizes[0] / HDIM;
    int nE  = in_sizes[1];
    int nB  = out_size / 10;
    int npg = nN / nB;

    int n4        = nN * (HDIM / 4);
    int initBlks  = (n4 + 255) / 256;
    long edgeThr  = (long)nE * 32;
    int edgeBlks  = (int)((edgeThr + 255) / 256);
    int mlpBlks   = (nN + 63) / 64;

    // head 0: pooling of raw features
    pool_kernel<<<nB, 128>>>(x, 0, 0, npg, nN);

    int insel = 0;  // 0 = external x, 1 = g_hA, 2 = g_hB
    for (int l = 0; l < 4; ++l) {
        const float *W1, *b1, *g1, *bt1, *W2, *b2, *go, *bo;
        if (l == 0) {
            W1 = pre_W1; b1 = pre_b1; g1 = pre_g1; bt1 = pre_bt1;
            W2 = pre_W2; b2 = pre_b2; go = pre_go; bo = pre_bo;
        } else {
            int i = l - 1;
            W1 = mlp_W1 + (size_t)i * HDIM * HDIM; b1 = mlp_b1 + i * HDIM;
            g1 = mlp_g1 + i * HDIM;                bt1 = mlp_bt1 + i * HDIM;
            W2 = mlp_W2 + (size_t)i * HDIM * HDIM; b2 = mlp_b2 + i * HDIM;
            go = bn_g + i * HDIM;                  bo = bn_bt + i * HDIM;
        }
        int outsel = (insel == 1) ? 2 : 1;

        init_agg_kernel<<<initBlks, 256>>>(x, insel, eps, l, n4);
        edge_agg_kernel<<<edgeBlks, 256>>>(x, insel, esrc, edst, nE);
        mlp_kernel<<<mlpBlks, 256>>>(nullptr, outsel,
                                     W1, b1, g1, bt1, W2, b2, go, bo, nN);
        pool_kernel<<<nB, 128>>>(x, outsel, l + 1, npg, nN);
        insel = outsel;
    }

    score_kernel<<<nB, 320>>>(pred_W0, pred_b0, pred_W, pred_b, out, nB);
}

// round 2
// speedup vs baseline: 1.4456x; 1.4456x over previous
#include <cuda_runtime.h>

#define MAXN 100000
#define MAXE 1600000
#define HDIM 128
#define MAXB 512
#define NHEADS 5
#define XS 132   // padded Xs row stride (floats): keeps 16B alignment, avoids bank conflicts

// ---------------- scratch (device globals; no allocation allowed) ----------
__device__ float g_agg[(size_t)MAXN * HDIM];
__device__ float g_hA [(size_t)MAXN * HDIM];
__device__ float g_hB [(size_t)MAXN * HDIM];
__device__ float g_pool[NHEADS * MAXB * HDIM];
__device__ int   g_deg[MAXN];
__device__ int   g_rowptr[MAXN + 1];
__device__ int   g_cursor[MAXN];
__device__ int   g_csr[MAXE];
__device__ int   g_blocksum[1024];
__device__ int   g_blockoff[1024];

__device__ __forceinline__ const float* sel_in(int s, const float* ext) {
    return s == 1 ? g_hA : (s == 2 ? g_hB : ext);
}

// ======================= CSR build (once per launch) =======================
__global__ void zero_deg_kernel(int nN) {
    int i = blockIdx.x * blockDim.x + threadIdx.x;
    if (i < nN) g_deg[i] = 0;
}

__global__ void count_kernel(const int* __restrict__ dst, int nE) {
    int e = blockIdx.x * blockDim.x + threadIdx.x;
    if (e < nE) atomicAdd(&g_deg[dst[e]], 1);
}

// per-1024 block scan of degrees -> exclusive (block-local) into rowptr, block totals
__global__ void scanA_kernel(int nN) {
    __shared__ int sh[1024];
    int tid = threadIdx.x;
    int i = blockIdx.x * 1024 + tid;
    int v = (i < nN) ? g_deg[i] : 0;
    sh[tid] = v;
    __syncthreads();
    #pragma unroll
    for (int off = 1; off < 1024; off <<= 1) {
        int a = sh[tid];
        int b = (tid >= off) ? sh[tid - off] : 0;
        __syncthreads();
        sh[tid] = a + b;
        __syncthreads();
    }
    int incl = sh[tid];
    if (i < nN) g_rowptr[i] = incl - v;           // block-local exclusive
    if (tid == 1023) g_blocksum[blockIdx.x] = incl;
}

__global__ void scanB_kernel(int nblocks, int nN) {
    __shared__ int sh[1024];
    int tid = threadIdx.x;
    int v = (tid < nblocks) ? g_blocksum[tid] : 0;
    sh[tid] = v;
    __syncthreads();
    #pragma unroll
    for (int off = 1; off < 1024; off <<= 1) {
        int a = sh[tid];
        int b = (tid >= off) ? sh[tid - off] : 0;
        __syncthreads();
        sh[tid] = a + b;
        __syncthreads();
    }
    int incl = sh[tid];
    if (tid < nblocks) g_blockoff[tid] = incl - v;
    if (tid == nblocks - 1) g_rowptr[nN] = incl;  // grand total
}

__global__ void scanC_kernel(int nN) {
    int i = blockIdx.x * blockDim.x + threadIdx.x;
    if (i < nN) {
        int r = g_rowptr[i] + g_blockoff[i >> 10];
        g_rowptr[i] = r;
        g_cursor[i] = r;
    }
}

__global__ void fill_kernel(const int* __restrict__ src,
                            const int* __restrict__ dst, int nE) {
    int e = blockIdx.x * blockDim.x + threadIdx.x;
    if (e < nE) {
        int d = dst[e];
        int pos = atomicAdd(&g_cursor[d], 1);
        g_csr[pos] = src[e];
    }
}

// ======= aggregation: pooled = sum_{s in N(d)} h[s] + (1+eps)*h[d] =========
// one warp per node; lane covers 4 floats; no atomics (CSR gather)
__global__ void __launch_bounds__(256)
gather_agg_kernel(const float* __restrict__ ext, int sel,
                  const float* __restrict__ eps, int layer, int nN) {
    int warp = (blockIdx.x * blockDim.x + threadIdx.x) >> 5;
    if (warp >= nN) return;
    const float* h = sel_in(sel, ext);
    int lane4 = (threadIdx.x & 31) * 4;
    float c = 1.0f + __ldg(eps + layer);

    float4 a0 = *(const float4*)(h + (size_t)warp * HDIM + lane4);
    a0.x *= c; a0.y *= c; a0.z *= c; a0.w *= c;
    float4 a1 = make_float4(0.f, 0.f, 0.f, 0.f);

    int beg = g_rowptr[warp], end = g_rowptr[warp + 1];
    int i = beg;
    for (; i + 2 <= end; i += 2) {
        int s0 = g_csr[i], s1 = g_csr[i + 1];
        float4 v0 = *(const float4*)(h + (size_t)s0 * HDIM + lane4);
        float4 v1 = *(const float4*)(h + (size_t)s1 * HDIM + lane4);
        a0.x += v0.x; a0.y += v0.y; a0.z += v0.z; a0.w += v0.w;
        a1.x += v1.x; a1.y += v1.y; a1.z += v1.z; a1.w += v1.w;
    }
    if (i < end) {
        int s0 = g_csr[i];
        float4 v0 = *(const float4*)(h + (size_t)s0 * HDIM + lane4);
        a0.x += v0.x; a0.y += v0.y; a0.z += v0.z; a0.w += v0.w;
    }
    a0.x += a1.x; a0.y += a1.y; a0.z += a1.z; a0.w += a1.w;
    *(float4*)(g_agg + (size_t)warp * HDIM + lane4) = a0;
}

// ================= fused GIN MLP: 128x128 tile, 8x8 microtile ===============
// Y = relu(go*(relu(g1*(X@W1+b1)+bt1)@W2+b2)+bo), X = g_agg
// 256 threads: tx = t&15 -> col block c0=tx*8; ty = t>>4 -> rows {ty + 16r}
__global__ void __launch_bounds__(256, 2)
mlp_kernel(int outsel,
           const float* __restrict__ W1, const float* __restrict__ b1,
           const float* __restrict__ g1, const float* __restrict__ bt1,
           const float* __restrict__ W2, const float* __restrict__ b2,
           const float* __restrict__ go, const float* __restrict__ bo,
           int nNodes) {
    extern __shared__ float smem[];
    float* Xs = smem;                  // 128 x XS
    float* Ws = smem + 128 * XS;       // 32 x 128 (K-chunk of W)

    int t  = threadIdx.x;
    int tx = t & 15, ty = t >> 4;
    int c0 = tx * 8;
    int m0 = blockIdx.x * 128;

    // load X tile
    {
        const float4* Xg = (const float4*)(g_agg + (size_t)m0 * HDIM);
        #pragma unroll
        for (int i = t; i < 128 * 32; i += 256) {
            int row = i >> 5, c4 = i & 31;
            float4 v = (m0 + row < nNodes) ? Xg[i] : make_float4(0.f, 0.f, 0.f, 0.f);
            *(float4*)&Xs[row * XS + c4 * 4] = v;
        }
    }

    float acc[8][8];
    #pragma unroll
    for (int r = 0; r < 8; ++r)
        #pragma unroll
        for (int i = 0; i < 8; ++i) acc[r][i] = 0.f;

    // ---- GEMM1 ----
    for (int kc = 0; kc < HDIM; kc += 32) {
        __syncthreads();
        const float4* Wg = (const float4*)(W1 + kc * HDIM);
        #pragma unroll
        for (int i = t; i < 32 * 32; i += 256) ((float4*)Ws)[i] = Wg[i];
        __syncthreads();
        #pragma unroll
        for (int kk = 0; kk < 32; kk += 4) {
            float4 xv[8];
            #pragma unroll
            for (int r = 0; r < 8; ++r)
                xv[r] = *(const float4*)&Xs[(ty + r * 16) * XS + kc + kk];
            #pragma unroll
            for (int j = 0; j < 4; ++j) {
                float4 wa = *(const float4*)&Ws[(kk + j) * HDIM + c0];
                float4 wb = *(const float4*)&Ws[(kk + j) * HDIM + c0 + 4];
                #pragma unroll
                for (int r = 0; r < 8; ++r) {
                    float x = (j == 0) ? xv[r].x : (j == 1) ? xv[r].y
                            : (j == 2) ? xv[r].z : xv[r].w;
                    acc[r][0] = fmaf(x, wa.x, acc[r][0]);
                    acc[r][1] = fmaf(x, wa.y, acc[r][1]);
                    acc[r][2] = fmaf(x, wa.z, acc[r][2]);
                    acc[r][3] = fmaf(x, wa.w, acc[r][3]);
                    acc[r][4] = fmaf(x, wb.x, acc[r][4]);
                    acc[r][5] = fmaf(x, wb.y, acc[r][5]);
                    acc[r][6] = fmaf(x, wb.z, acc[r][6]);
                    acc[r][7] = fmaf(x, wb.w, acc[r][7]);
                }
            }
        }
    }
    __syncthreads();   // all Xs reads done before overwrite

    // epilogue1: h1 = relu(g1*(acc+b1)+bt1) -> Xs
    {
        float4 Ba = *(const float4*)&b1[c0],  Bb = *(const float4*)&b1[c0 + 4];
        float4 Ga = *(const float4*)&g1[c0],  Gb = *(const float4*)&g1[c0 + 4];
        float4 Ta = *(const float4*)&bt1[c0], Tb = *(const float4*)&bt1[c0 + 4];
        #pragma unroll
        for (int r = 0; r < 8; ++r) {
            float4 va, vb;
            va.x = fmaxf(Ga.x * (acc[r][0] + Ba.x) + Ta.x, 0.f);
            va.y = fmaxf(Ga.y * (acc[r][1] + Ba.y) + Ta.y, 0.f);
            va.z = fmaxf(Ga.z * (acc[r][2] + Ba.z) + Ta.z, 0.f);
            va.w = fmaxf(Ga.w * (acc[r][3] + Ba.w) + Ta.w, 0.f);
            vb.x = fmaxf(Gb.x * (acc[r][4] + Bb.x) + Tb.x, 0.f);
            vb.y = fmaxf(Gb.y * (acc[r][5] + Bb.y) + Tb.y, 0.f);
            vb.z = fmaxf(Gb.z * (acc[r][6] + Bb.z) + Tb.z, 0.f);
            vb.w = fmaxf(Gb.w * (acc[r][7] + Bb.w) + Tb.w, 0.f);
            int row = ty + r * 16;
            *(float4*)&Xs[row * XS + c0]     = va;
            *(float4*)&Xs[row * XS + c0 + 4] = vb;
            #pragma unroll
            for (int i = 0; i < 8; ++i) acc[r][i] = 0.f;
        }
    }

    // ---- GEMM2 ----
    for (int kc = 0; kc < HDIM; kc += 32) {
        __syncthreads();
        const float4* Wg = (const float4*)(W2 + kc * HDIM);
        #pragma unroll
        for (int i = t; i < 32 * 32; i += 256) ((float4*)Ws)[i] = Wg[i];
        __syncthreads();
        #pragma unroll
        for (int kk = 0; kk < 32; kk += 4) {
            float4 xv[8];
            #pragma unroll
            for (int r = 0; r < 8; ++r)
                xv[r] = *(const float4*)&Xs[(ty + r * 16) * XS + kc + kk];
            #pragma unroll
            for (int j = 0; j < 4; ++j) {
                float4 wa = *(const float4*)&Ws[(kk + j) * HDIM + c0];
                float4 wb = *(const float4*)&Ws[(kk + j) * HDIM + c0 + 4];
                #pragma unroll
                for (int r = 0; r < 8; ++r) {
                    float x = (j == 0) ? xv[r].x : (j == 1) ? xv[r].y
                            : (j == 2) ? xv[r].z : xv[r].w;
                    acc[r][0] = fmaf(x, wa.x, acc[r][0]);
                    acc[r][1] = fmaf(x, wa.y, acc[r][1]);
                    acc[r][2] = fmaf(x, wa.z, acc[r][2]);
                    acc[r][3] = fmaf(x, wa.w, acc[r][3]);
                    acc[r][4] = fmaf(x, wb.x, acc[r][4]);
                    acc[r][5] = fmaf(x, wb.y, acc[r][5]);
                    acc[r][6] = fmaf(x, wb.z, acc[r][6]);
                    acc[r][7] = fmaf(x, wb.w, acc[r][7]);
                }
            }
        }
    }

    // epilogue2: y = relu(go*(acc+b2)+bo) -> global
    {
        float* Y = (outsel == 1) ? g_hA : g_hB;
        float4 Ba = *(const float4*)&b2[c0], Bb = *(const float4*)&b2[c0 + 4];
        float4 Ga = *(const float4*)&go[c0], Gb = *(const float4*)&go[c0 + 4];
        float4 Oa = *(const float4*)&bo[c0], Ob = *(const float4*)&bo[c0 + 4];
        #pragma unroll
        for (int r = 0; r < 8; ++r) {
            int row = m0 + ty + r * 16;
            if (row < nNodes) {
                float4 va, vb;
                va.x = fmaxf(Ga.x * (acc[r][0] + Ba.x) + Oa.x, 0.f);
                va.y = fmaxf(Ga.y * (acc[r][1] + Ba.y) + Oa.y, 0.f);
                va.z = fmaxf(Ga.z * (acc[r][2] + Ba.z) + Oa.z, 0.f);
                va.w = fmaxf(Ga.w * (acc[r][3] + Ba.w) + Oa.w, 0.f);
                vb.x = fmaxf(Gb.x * (acc[r][4] + Bb.x) + Ob.x, 0.f);
                vb.y = fmaxf(Gb.y * (acc[r][5] + Bb.y) + Ob.y, 0.f);
                vb.z = fmaxf(Gb.z * (acc[r][6] + Bb.z) + Ob.z, 0.f);
                vb.w = fmaxf(Gb.w * (acc[r][7] + Bb.w) + Ob.w, 0.f);
                *(float4*)&Y[(size_t)row * HDIM + c0]     = va;
                *(float4*)&Y[(size_t)row * HDIM + c0 + 4] = vb;
            }
        }
    }
}

// ---------------- graph pooling: contiguous segment sum -----------------
__global__ void pool_kernel(const float* __restrict__ ext, int sel,
                            int head, int npg, int nN) {
    const float* h = sel_in(sel, ext);
    int b = blockIdx.x;
    int j = threadIdx.x;  // 128 threads
    int n = b * npg;
    int end = n + npg; if (end > nN) end = nN;
    float s0 = 0.f, s1 = 0.f, s2 = 0.f, s3 = 0.f;
    for (; n + 4 <= end; n += 4) {
        s0 += h[(size_t)(n + 0) * HDIM + j];
        s1 += h[(size_t)(n + 1) * HDIM + j];
        s2 += h[(size_t)(n + 2) * HDIM + j];
        s3 += h[(size_t)(n + 3) * HDIM + j];
    }
    for (; n < end; ++n) s0 += h[(size_t)n * HDIM + j];
    g_pool[(head * gridDim.x + b) * HDIM + j] = s0 + s1 + s2 + s3;
}

// ---------------- heads -------------------------------------------------
__global__ void score_kernel(const float* __restrict__ W0,
                             const float* __restrict__ b0,
                             const float* __restrict__ W,
                             const float* __restrict__ bres,
                             float* __restrict__ out, int nB) {
    int b = blockIdx.x;
    int o = threadIdx.x >> 5;    // 10 warps
    int lane = threadIdx.x & 31;
    float s = 0.f;
    #pragma unroll
    for (int j = lane; j < HDIM; j += 32)
        s += g_pool[b * HDIM + j] * W0[j * 10 + o];
    #pragma unroll
    for (int k = 0; k < 4; ++k)
        #pragma unroll
        for (int j = lane; j < HDIM; j += 32)
            s += g_pool[((k + 1) * nB + b) * HDIM + j] * W[(k * HDIM + j) * 10 + o];
    #pragma unroll
    for (int off = 16; off; off >>= 1)
        s += __shfl_down_sync(0xffffffffu, s, off);
    if (lane == 0) {
        float bias = b0[o];
        #pragma unroll
        for (int k = 0; k < 4; ++k) bias += bres[k * 10 + o];
        out[b * 10 + o] = s + bias;
    }
}

// ---------------- launch ------------------------------------------------
extern "C" void kernel_launch(void* const* d_in, const int* in_sizes, int n_in,
                              void* d_out, int out_size) {
    const float* x        = (const float*)d_in[0];
    const int*   esrc     = (const int*)  d_in[1];
    const int*   edst     = (const int*)  d_in[2];
    const float* eps      = (const float*)d_in[4];
    const float* pre_W1   = (const float*)d_in[5];
    const float* pre_b1   = (const float*)d_in[6];
    const float* pre_g1   = (const float*)d_in[7];
    const float* pre_bt1  = (const float*)d_in[8];
    const float* pre_W2   = (const float*)d_in[9];
    const float* pre_b2   = (const float*)d_in[10];
    const float* pre_go   = (const float*)d_in[11];
    const float* pre_bo   = (const float*)d_in[12];
    const float* mlp_W1   = (const float*)d_in[13];
    const float* mlp_b1   = (const float*)d_in[14];
    const float* mlp_g1   = (const float*)d_in[15];
    const float* mlp_bt1  = (const float*)d_in[16];
    const float* mlp_W2   = (const float*)d_in[17];
    const float* mlp_b2   = (const float*)d_in[18];
    const float* bn_g     = (const float*)d_in[19];
    const float* bn_bt    = (const float*)d_in[20];
    const float* pred_W0  = (const float*)d_in[21];
    const float* pred_b0  = (const float*)d_in[22];
    const float* pred_W   = (const float*)d_in[23];
    const float* pred_b   = (const float*)d_in[24];
    float* out = (float*)d_out;

    int nN  = in_sizes[0] / HDIM;
    int nE  = in_sizes[1];
    int nB  = out_size / 10;
    int npg = nN / nB;

    const int mlpSmem = (128 * XS + 32 * HDIM) * (int)sizeof(float);  // 83968
    cudaFuncSetAttribute(mlp_kernel, cudaFuncAttributeMaxDynamicSharedMemorySize, mlpSmem);

    int scanBlks = (nN + 1023) / 1024;

    // ---- CSR build (once) ----
    zero_deg_kernel<<<(nN + 255) / 256, 256>>>(nN);
    count_kernel<<<(nE + 255) / 256, 256>>>(edst, nE);
    scanA_kernel<<<scanBlks, 1024>>>(nN);
    scanB_kernel<<<1, 1024>>>(scanBlks, nN);
    scanC_kernel<<<(nN + 255) / 256, 256>>>(nN);
    fill_kernel<<<(nE + 255) / 256, 256>>>(esrc, edst, nE);

    // head 0: pooling of raw features
    pool_kernel<<<nB, 128>>>(x, 0, 0, npg, nN);

    int gatherBlks = (nN * 32 + 255) / 256;
    int mlpBlks    = (nN + 127) / 128;

    int insel = 0;  // 0 = external x, 1 = g_hA, 2 = g_hB
    for (int l = 0; l < 4; ++l) {
        const float *W1, *b1, *g1, *bt1, *W2, *b2, *go, *bo;
        if (l == 0) {
            W1 = pre_W1; b1 = pre_b1; g1 = pre_g1; bt1 = pre_bt1;
            W2 = pre_W2; b2 = pre_b2; go = pre_go; bo = pre_bo;
        } else {
            int i = l - 1;
            W1 = mlp_W1 + (size_t)i * HDIM * HDIM; b1 = mlp_b1 + i * HDIM;
            g1 = mlp_g1 + i * HDIM;                bt1 = mlp_bt1 + i * HDIM;
            W2 = mlp_W2 + (size_t)i * HDIM * HDIM; b2 = mlp_b2 + i * HDIM;
            go = bn_g + i * HDIM;                  bo = bn_bt + i * HDIM;
        }
        int outsel = (insel == 1) ? 2 : 1;

        gather_agg_kernel<<<gatherBlks, 256>>>(x, insel, eps, l, nN);
        mlp_kernel<<<mlpBlks, 256, mlpSmem>>>(outsel,
                                              W1, b1, g1, bt1, W2, b2, go, bo, nN);
        pool_kernel<<<nB, 128>>>(x, outsel, l + 1, npg, nN);
        insel = outsel;
    }

    score_kernel<<<nB, 320>>>(pred_W0, pred_b0, pred_W, pred_b, out, nB);
}